// round 5
// baseline (speedup 1.0000x reference)
#include <cuda_runtime.h>
#include <math.h>
#include <stdint.h>

#define N_LEVELS 16
#define TABLE_SIZE (1u << 19)
#define HASH_MASK 0x7FFFFu
#define NPTS 1048576
#define PRIME_Y 2654435761u
#define PRIME_Z 805459861u

#define BINS_PER_AXIS 64
#define NBINS (BINS_PER_AXIS * BINS_PER_AXIS * BINS_PER_AXIS)

struct ResArr { float r[N_LEVELS]; };

// Scratch (static device globals: allowed; no allocation APIs)
__device__ unsigned d_count[NBINS];   // counts, then exclusive offsets (in place)
__device__ unsigned d_slot[NPTS];     // (bin << 14) | rank-within-bin
__device__ float4   d_xs[NPTS];       // reordered points: (x, y, z, bits(point_id))
__device__ unsigned d_cursor;

__device__ __forceinline__ unsigned spread3(unsigned v) {
    v = (v | (v << 16)) & 0x030000FFu;
    v = (v | (v << 8))  & 0x0300F00Fu;
    v = (v | (v << 4))  & 0x030C30C3u;
    v = (v | (v << 2))  & 0x09249249u;
    return v;
}

__device__ __forceinline__ unsigned bin_of(float px, float py, float pz,
                                           float b0x, float b0y, float b0z,
                                           float ivx, float ivy, float ivz) {
    float ux = (px - b0x) * ivx;
    float uy = (py - b0y) * ivy;
    float uz = (pz - b0z) * ivz;
    int bx = min(BINS_PER_AXIS - 1, max(0, (int)floorf(ux * BINS_PER_AXIS)));
    int by = min(BINS_PER_AXIS - 1, max(0, (int)floorf(uy * BINS_PER_AXIS)));
    int bz = min(BINS_PER_AXIS - 1, max(0, (int)floorf(uz * BINS_PER_AXIS)));
    // Morton (z-order) bin index: compact 3D locality in sorted order
    return spread3((unsigned)bx) | (spread3((unsigned)by) << 1) | (spread3((unsigned)bz) << 2);
}

__global__ void k_zero() {
    int i = blockIdx.x * blockDim.x + threadIdx.x;
    if (i < NBINS) d_count[i] = 0u;
    if (i == 0) d_cursor = 0u;
}

__global__ void k_count(const float* __restrict__ x,
                        const float* __restrict__ bbox,
                        float* __restrict__ mask_out, int write_mask) {
    int i = blockIdx.x * blockDim.x + threadIdx.x;
    if (i >= NPTS) return;
    float b0x = __ldg(bbox + 0), b0y = __ldg(bbox + 1), b0z = __ldg(bbox + 2);
    float b1x = __ldg(bbox + 3), b1y = __ldg(bbox + 4), b1z = __ldg(bbox + 5);
    float px = __ldg(x + 3 * i + 0);
    float py = __ldg(x + 3 * i + 1);
    float pz = __ldg(x + 3 * i + 2);
    if (write_mask) {
        bool m = (px >= b0x) && (px <= b1x) && (py >= b0y) && (py <= b1y) &&
                 (pz >= b0z) && (pz <= b1z);
        mask_out[i] = m ? 1.0f : 0.0f;
    }
    float ivx = 1.0f / (b1x - b0x), ivy = 1.0f / (b1y - b0y), ivz = 1.0f / (b1z - b0z);
    unsigned b = bin_of(px, py, pz, b0x, b0y, b0z, ivx, ivy, ivz);
    unsigned rank = atomicAdd(&d_count[b], 1u);
    d_slot[i] = (b << 14) | (rank & 0x3FFFu);
}

__global__ void k_offsets() {
    int t = blockIdx.x * blockDim.x + threadIdx.x;
    if (t >= NBINS) return;
    int lane = threadIdx.x & 31;
    unsigned v = d_count[t];
    unsigned pre = v;
#pragma unroll
    for (int d = 1; d < 32; d <<= 1) {
        unsigned n = __shfl_up_sync(0xFFFFFFFFu, pre, d);
        if (lane >= d) pre += n;
    }
    unsigned total = __shfl_sync(0xFFFFFFFFu, pre, 31);
    unsigned base = 0;
    if (lane == 31) base = atomicAdd(&d_cursor, total);
    base = __shfl_sync(0xFFFFFFFFu, base, 31);
    d_count[t] = base + pre - v;   // exclusive offset
}

__global__ void k_scatter(const float* __restrict__ x) {
    int i = blockIdx.x * blockDim.x + threadIdx.x;
    if (i >= NPTS) return;
    unsigned s = d_slot[i];
    unsigned b = s >> 14;
    unsigned rank = s & 0x3FFFu;
    unsigned dst = d_count[b] + rank;
    float px = __ldg(x + 3 * i + 0);    // coalesced read
    float py = __ldg(x + 3 * i + 1);
    float pz = __ldg(x + 3 * i + 2);
    d_xs[dst] = make_float4(px, py, pz, __uint_as_float((unsigned)i));
}

// Block = 512 threads = 16 warps. Warp w computes level w for 32 consecutive
// sorted points -> every gather instruction dedups across 32 spatially-adjacent
// points (vs 8 before). Results staged through smem so global stores stay
// 128B-per-point coalesced.
__global__ void __launch_bounds__(512) hash_embed_kernel(
    const float2* __restrict__ emb,
    const float* __restrict__ bbox,
    float* __restrict__ out,
    ResArr res)
{
    __shared__ float2 s_feat[32][17];   // [point][level], padded: conflict-free
    __shared__ unsigned s_id[32];

    int w    = threadIdx.x >> 5;        // level = warp id
    int lane = threadIdx.x & 31;        // point within block
    int point = blockIdx.x * 32 + lane;

    float4 P = __ldg(&d_xs[point]);     // coalesced per warp
    float px = P.x, py = P.y, pz = P.z;
    if (w == 0) s_id[lane] = __float_as_uint(P.w);

    float b0x = __ldg(bbox + 0), b0y = __ldg(bbox + 1), b0z = __ldg(bbox + 2);
    float b1x = __ldg(bbox + 3), b1y = __ldg(bbox + 4), b1z = __ldg(bbox + 5);

    float cx = fminf(fmaxf(px, b0x), b1x);
    float cy = fminf(fmaxf(py, b0y), b1y);
    float cz = fminf(fmaxf(pz, b0z), b1z);

    float invx = 1.0f / (b1x - b0x);
    float invy = 1.0f / (b1y - b0y);
    float invz = 1.0f / (b1z - b0z);

    float r = res.r[w];

    float ux = (cx - b0x) * invx * r;
    float uy = (cy - b0y) * invy * r;
    float uz = (cz - b0z) * invz * r;
    float gx = (px - b0x) * invx;   // w numerator uses UNCLIPPED x (matches ref)
    float gy = (py - b0y) * invy;
    float gz = (pz - b0z) * invz;

    float fx = floorf(ux), fy = floorf(uy), fz = floorf(uz);
    float wx = fmaf(gx, r, -fx);
    float wy = fmaf(gy, r, -fy);
    float wz = fmaf(gz, r, -fz);

    unsigned ix0 = (unsigned)(int)fx;
    unsigned iy  = (unsigned)(int)fy;
    unsigned iz  = (unsigned)(int)fz;
    unsigned hy0 = iy * PRIME_Y, hy1 = hy0 + PRIME_Y;   // (y+1)*P == y*P+P (u32 wrap)
    unsigned hz0 = iz * PRIME_Z, hz1 = hz0 + PRIME_Z;

    // corner order matches _OFFSETS: k = (y0z0, y0z1, y1z0, y1z1)
    unsigned hyz0 = hy0 ^ hz0;
    unsigned hyz1 = hy0 ^ hz1;
    unsigned hyz2 = hy1 ^ hz0;
    unsigned hyz3 = hy1 ^ hz1;

    const float2* t2 = emb + (size_t)w * TABLE_SIZE;

    float2 a0, a1, a2, a3;   // x0 corners (v0..v3)
    float2 b0, b1, b2, b3;   // x1 corners (v4..v7)

    if ((ix0 & 1u) == 0u) {
        // ix0 even: {idx, idx^1} form an aligned float4 pair -> one LDG.128
        const float4* t4 = (const float4*)t2;
        unsigned i0 = (ix0 ^ hyz0) & HASH_MASK;
        unsigned i1 = (ix0 ^ hyz1) & HASH_MASK;
        unsigned i2 = (ix0 ^ hyz2) & HASH_MASK;
        unsigned i3 = (ix0 ^ hyz3) & HASH_MASK;
        float4 p0 = __ldg(t4 + (i0 >> 1));
        float4 p1 = __ldg(t4 + (i1 >> 1));
        float4 p2 = __ldg(t4 + (i2 >> 1));
        float4 p3 = __ldg(t4 + (i3 >> 1));
        bool h0 = i0 & 1u, h1 = i1 & 1u, h2 = i2 & 1u, h3 = i3 & 1u;
        a0 = h0 ? make_float2(p0.z, p0.w) : make_float2(p0.x, p0.y);
        b0 = h0 ? make_float2(p0.x, p0.y) : make_float2(p0.z, p0.w);
        a1 = h1 ? make_float2(p1.z, p1.w) : make_float2(p1.x, p1.y);
        b1 = h1 ? make_float2(p1.x, p1.y) : make_float2(p1.z, p1.w);
        a2 = h2 ? make_float2(p2.z, p2.w) : make_float2(p2.x, p2.y);
        b2 = h2 ? make_float2(p2.x, p2.y) : make_float2(p2.z, p2.w);
        a3 = h3 ? make_float2(p3.z, p3.w) : make_float2(p3.x, p3.y);
        b3 = h3 ? make_float2(p3.x, p3.y) : make_float2(p3.z, p3.w);
    } else {
        unsigned ix1 = ix0 + 1u;
        a0 = __ldg(t2 + ((ix0 ^ hyz0) & HASH_MASK));
        a1 = __ldg(t2 + ((ix0 ^ hyz1) & HASH_MASK));
        a2 = __ldg(t2 + ((ix0 ^ hyz2) & HASH_MASK));
        a3 = __ldg(t2 + ((ix0 ^ hyz3) & HASH_MASK));
        b0 = __ldg(t2 + ((ix1 ^ hyz0) & HASH_MASK));
        b1 = __ldg(t2 + ((ix1 ^ hyz1) & HASH_MASK));
        b2 = __ldg(t2 + ((ix1 ^ hyz2) & HASH_MASK));
        b3 = __ldg(t2 + ((ix1 ^ hyz3) & HASH_MASK));
    }

    float ox = 1.0f - wx, oy = 1.0f - wy, oz = 1.0f - wz;

    float c00a = a0.x * ox + b0.x * wx, c00b = a0.y * ox + b0.y * wx;
    float c01a = a1.x * ox + b1.x * wx, c01b = a1.y * ox + b1.y * wx;
    float c10a = a2.x * ox + b2.x * wx, c10b = a2.y * ox + b2.y * wx;
    float c11a = a3.x * ox + b3.x * wx, c11b = a3.y * ox + b3.y * wx;

    float c0a = c00a * oy + c10a * wy, c0b = c00b * oy + c10b * wy;
    float c1a = c01a * oy + c11a * wy, c1b = c01b * oy + c11b * wy;

    s_feat[lane][w] = make_float2(c0a * oz + c1a * wz, c0b * oz + c1b * wz);

    __syncthreads();

    // Coalesced write-out: 256 threads cover 32 points x 8 float4 chunks.
    int t = threadIdx.x;
    if (t < 256) {
        int pt = t >> 3, c = t & 7;          // point, chunk (levels 2c, 2c+1)
        float2 u = s_feat[pt][2 * c];
        float2 v = s_feat[pt][2 * c + 1];
        unsigned opid = s_id[pt];
        float4* o = (float4*)(out + (size_t)opid * 32 + c * 4);
        *o = make_float4(u.x, u.y, v.x, v.y);
    }
}

extern "C" void kernel_launch(void* const* d_in, const int* in_sizes, int n_in,
                              void* d_out, int out_size) {
    const float*  x    = (const float*)d_in[0];
    const float2* emb  = (const float2*)d_in[1];
    const float*  bbox = (const float*)d_in[2];
    float* out = (float*)d_out;

    // Resolutions: replicate numpy's double-precision exp/log/pow exactly.
    ResArr res;
    double b = exp((log(512.0) - log(16.0)) / 15.0);
    for (int l = 0; l < N_LEVELS; ++l) {
        res.r[l] = (float)floor(16.0 * pow(b, (double)l));
    }

    int write_mask = (out_size >= (int)(NPTS * 32 + NPTS)) ? 1 : 0;
    float* mask_out = out + (size_t)NPTS * 32;

    k_zero<<<(NBINS + 255) / 256, 256>>>();
    k_count<<<(NPTS + 255) / 256, 256>>>(x, bbox, mask_out, write_mask);
    k_offsets<<<(NBINS + 255) / 256, 256>>>();
    k_scatter<<<(NPTS + 255) / 256, 256>>>(x);

    hash_embed_kernel<<<NPTS / 32, 512>>>(emb, bbox, out, res);
}

// round 6
// speedup vs baseline: 1.2077x; 1.2077x over previous
#include <cuda_runtime.h>
#include <math.h>
#include <stdint.h>

#define N_LEVELS 16
#define TABLE_SIZE (1u << 19)
#define HASH_MASK 0x7FFFFu
#define NPTS 1048576
#define PRIME_Y 2654435761u
#define PRIME_Z 805459861u

#define BINS_PER_AXIS 64
#define NBINS (BINS_PER_AXIS * BINS_PER_AXIS * BINS_PER_AXIS)

struct ResArr { float r[N_LEVELS]; };

// Scratch (static device globals: allowed; no allocation APIs)
__device__ unsigned d_count[NBINS];   // counts, then exclusive offsets (in place)
__device__ unsigned d_slot[NPTS];     // (bin << 14) | rank-within-bin
__device__ float4   d_xs[NPTS];       // reordered points: (x, y, z, bits(point_id))
__device__ unsigned d_cursor;

__device__ __forceinline__ unsigned spread3(unsigned v) {
    v = (v | (v << 16)) & 0x030000FFu;
    v = (v | (v << 8))  & 0x0300F00Fu;
    v = (v | (v << 4))  & 0x030C30C3u;
    v = (v | (v << 2))  & 0x09249249u;
    return v;
}

__device__ __forceinline__ unsigned bin_of(float px, float py, float pz,
                                           float b0x, float b0y, float b0z,
                                           float ivx, float ivy, float ivz) {
    float ux = (px - b0x) * ivx;
    float uy = (py - b0y) * ivy;
    float uz = (pz - b0z) * ivz;
    int bx = min(BINS_PER_AXIS - 1, max(0, (int)floorf(ux * BINS_PER_AXIS)));
    int by = min(BINS_PER_AXIS - 1, max(0, (int)floorf(uy * BINS_PER_AXIS)));
    int bz = min(BINS_PER_AXIS - 1, max(0, (int)floorf(uz * BINS_PER_AXIS)));
    // Morton (z-order) bin index: compact 3D locality in sorted order
    return spread3((unsigned)bx) | (spread3((unsigned)by) << 1) | (spread3((unsigned)bz) << 2);
}

__global__ void k_zero() {
    int i = blockIdx.x * blockDim.x + threadIdx.x;
    if (i < NBINS) d_count[i] = 0u;
    if (i == 0) d_cursor = 0u;
}

__global__ void k_count(const float* __restrict__ x,
                        const float* __restrict__ bbox,
                        float* __restrict__ mask_out, int write_mask) {
    int i = blockIdx.x * blockDim.x + threadIdx.x;
    if (i >= NPTS) return;
    float b0x = __ldg(bbox + 0), b0y = __ldg(bbox + 1), b0z = __ldg(bbox + 2);
    float b1x = __ldg(bbox + 3), b1y = __ldg(bbox + 4), b1z = __ldg(bbox + 5);
    float px = __ldg(x + 3 * i + 0);
    float py = __ldg(x + 3 * i + 1);
    float pz = __ldg(x + 3 * i + 2);
    if (write_mask) {
        bool m = (px >= b0x) && (px <= b1x) && (py >= b0y) && (py <= b1y) &&
                 (pz >= b0z) && (pz <= b1z);
        mask_out[i] = m ? 1.0f : 0.0f;
    }
    float ivx = 1.0f / (b1x - b0x), ivy = 1.0f / (b1y - b0y), ivz = 1.0f / (b1z - b0z);
    unsigned b = bin_of(px, py, pz, b0x, b0y, b0z, ivx, ivy, ivz);
    unsigned rank = atomicAdd(&d_count[b], 1u);
    d_slot[i] = (b << 14) | (rank & 0x3FFFu);
}

__global__ void k_offsets() {
    int t = blockIdx.x * blockDim.x + threadIdx.x;
    if (t >= NBINS) return;
    int lane = threadIdx.x & 31;
    unsigned v = d_count[t];
    unsigned pre = v;
#pragma unroll
    for (int d = 1; d < 32; d <<= 1) {
        unsigned n = __shfl_up_sync(0xFFFFFFFFu, pre, d);
        if (lane >= d) pre += n;
    }
    unsigned total = __shfl_sync(0xFFFFFFFFu, pre, 31);
    unsigned base = 0;
    if (lane == 31) base = atomicAdd(&d_cursor, total);
    base = __shfl_sync(0xFFFFFFFFu, base, 31);
    d_count[t] = base + pre - v;   // exclusive offset
}

__global__ void k_scatter(const float* __restrict__ x) {
    int i = blockIdx.x * blockDim.x + threadIdx.x;
    if (i >= NPTS) return;
    unsigned s = d_slot[i];
    unsigned b = s >> 14;
    unsigned rank = s & 0x3FFFu;
    unsigned dst = d_count[b] + rank;
    float px = __ldg(x + 3 * i + 0);    // coalesced read
    float py = __ldg(x + 3 * i + 1);
    float pz = __ldg(x + 3 * i + 2);
    d_xs[dst] = make_float4(px, py, pz, __uint_as_float((unsigned)i));
}

// Thread = (point, level-quad lq). NEW lane mapping: lq is uniform across a
// warp, lane = point offset -> every gather instruction covers 32 consecutive
// Morton-sorted points at ONE level (max L1 address-merge population), while
// each thread still amortizes the prologue over 4 levels and keeps 32 loads
// in flight. No smem, no syncs.
__global__ void __launch_bounds__(256) hash_embed_kernel(
    const float2* __restrict__ emb,
    const float* __restrict__ bbox,
    float* __restrict__ out,
    ResArr res)
{
    int tid   = blockIdx.x * 256 + threadIdx.x;
    int gwarp = tid >> 5;
    int lane  = tid & 31;
    int lq    = gwarp & 3;
    int point = ((gwarp >> 2) << 5) + lane;   // 32 consecutive sorted points per warp

    float4 P = __ldg(&d_xs[point]);           // coalesced: 32 consecutive float4
    float px = P.x, py = P.y, pz = P.z;
    int p = (int)__float_as_uint(P.w);

    float b0x = __ldg(bbox + 0), b0y = __ldg(bbox + 1), b0z = __ldg(bbox + 2);
    float b1x = __ldg(bbox + 3), b1y = __ldg(bbox + 4), b1z = __ldg(bbox + 5);

    // clip to box
    float cx = fminf(fmaxf(px, b0x), b1x);
    float cy = fminf(fmaxf(py, b0y), b1y);
    float cz = fminf(fmaxf(pz, b0z), b1z);

    float invx = 1.0f / (b1x - b0x);
    float invy = 1.0f / (b1y - b0y);
    float invz = 1.0f / (b1z - b0z);

    float ux = (cx - b0x) * invx;
    float uy = (cy - b0y) * invy;
    float uz = (cz - b0z) * invz;
    float gx = (px - b0x) * invx;   // w numerator uses UNCLIPPED x (matches ref)
    float gy = (py - b0y) * invy;
    float gz = (pz - b0z) * invz;

    float acc[8];

#pragma unroll
    for (int j = 0; j < 4; ++j) {
        int level = lq * 4 + j;
        float r = res.r[level];

        float tx = ux * r, ty = uy * r, tz = uz * r;
        float fx = floorf(tx), fy = floorf(ty), fz = floorf(tz);
        float wx = fmaf(gx, r, -fx);
        float wy = fmaf(gy, r, -fy);
        float wz = fmaf(gz, r, -fz);

        unsigned ix0 = (unsigned)(int)fx;
        unsigned iy  = (unsigned)(int)fy;
        unsigned iz  = (unsigned)(int)fz;
        unsigned hy0 = iy * PRIME_Y, hy1 = hy0 + PRIME_Y;   // (y+1)*P == y*P+P (u32 wrap)
        unsigned hz0 = iz * PRIME_Z, hz1 = hz0 + PRIME_Z;

        // corner order matches _OFFSETS: k = (y0z0, y0z1, y1z0, y1z1)
        unsigned hyz0 = hy0 ^ hz0;
        unsigned hyz1 = hy0 ^ hz1;
        unsigned hyz2 = hy1 ^ hz0;
        unsigned hyz3 = hy1 ^ hz1;

        const float2* t2 = emb + (size_t)level * TABLE_SIZE;

        float2 a0, a1, a2, a3;   // x0 corners (v0..v3)
        float2 b0, b1, b2, b3;   // x1 corners (v4..v7)

        if ((ix0 & 1u) == 0u) {
            // ix0 even: {idx, idx^1} form an aligned float4 pair -> one LDG.128
            const float4* t4 = (const float4*)t2;
            unsigned i0 = (ix0 ^ hyz0) & HASH_MASK;
            unsigned i1 = (ix0 ^ hyz1) & HASH_MASK;
            unsigned i2 = (ix0 ^ hyz2) & HASH_MASK;
            unsigned i3 = (ix0 ^ hyz3) & HASH_MASK;
            float4 p0 = __ldg(t4 + (i0 >> 1));
            float4 p1 = __ldg(t4 + (i1 >> 1));
            float4 p2 = __ldg(t4 + (i2 >> 1));
            float4 p3 = __ldg(t4 + (i3 >> 1));
            bool h0 = i0 & 1u, h1 = i1 & 1u, h2 = i2 & 1u, h3 = i3 & 1u;
            a0 = h0 ? make_float2(p0.z, p0.w) : make_float2(p0.x, p0.y);
            b0 = h0 ? make_float2(p0.x, p0.y) : make_float2(p0.z, p0.w);
            a1 = h1 ? make_float2(p1.z, p1.w) : make_float2(p1.x, p1.y);
            b1 = h1 ? make_float2(p1.x, p1.y) : make_float2(p1.z, p1.w);
            a2 = h2 ? make_float2(p2.z, p2.w) : make_float2(p2.x, p2.y);
            b2 = h2 ? make_float2(p2.x, p2.y) : make_float2(p2.z, p2.w);
            a3 = h3 ? make_float2(p3.z, p3.w) : make_float2(p3.x, p3.y);
            b3 = h3 ? make_float2(p3.x, p3.y) : make_float2(p3.z, p3.w);
        } else {
            unsigned ix1 = ix0 + 1u;
            a0 = __ldg(t2 + ((ix0 ^ hyz0) & HASH_MASK));
            a1 = __ldg(t2 + ((ix0 ^ hyz1) & HASH_MASK));
            a2 = __ldg(t2 + ((ix0 ^ hyz2) & HASH_MASK));
            a3 = __ldg(t2 + ((ix0 ^ hyz3) & HASH_MASK));
            b0 = __ldg(t2 + ((ix1 ^ hyz0) & HASH_MASK));
            b1 = __ldg(t2 + ((ix1 ^ hyz1) & HASH_MASK));
            b2 = __ldg(t2 + ((ix1 ^ hyz2) & HASH_MASK));
            b3 = __ldg(t2 + ((ix1 ^ hyz3) & HASH_MASK));
        }

        float ox = 1.0f - wx, oy = 1.0f - wy, oz = 1.0f - wz;

        float c00a = a0.x * ox + b0.x * wx, c00b = a0.y * ox + b0.y * wx;
        float c01a = a1.x * ox + b1.x * wx, c01b = a1.y * ox + b1.y * wx;
        float c10a = a2.x * ox + b2.x * wx, c10b = a2.y * ox + b2.y * wx;
        float c11a = a3.x * ox + b3.x * wx, c11b = a3.y * ox + b3.y * wx;

        float c0a = c00a * oy + c10a * wy, c0b = c00b * oy + c10b * wy;
        float c1a = c01a * oy + c11a * wy, c1b = c01b * oy + c11b * wy;

        acc[j * 2 + 0] = c0a * oz + c1a * wz;
        acc[j * 2 + 1] = c0b * oz + c1b * wz;
    }

    // out[p][level*2+feat]: this thread owns 32 contiguous bytes -> 2x STG.128
    float4* o = (float4*)(out + (size_t)p * 32 + lq * 8);
    o[0] = make_float4(acc[0], acc[1], acc[2], acc[3]);
    o[1] = make_float4(acc[4], acc[5], acc[6], acc[7]);
}

extern "C" void kernel_launch(void* const* d_in, const int* in_sizes, int n_in,
                              void* d_out, int out_size) {
    const float*  x    = (const float*)d_in[0];
    const float2* emb  = (const float2*)d_in[1];
    const float*  bbox = (const float*)d_in[2];
    float* out = (float*)d_out;

    // Resolutions: replicate numpy's double-precision exp/log/pow exactly.
    ResArr res;
    double b = exp((log(512.0) - log(16.0)) / 15.0);
    for (int l = 0; l < N_LEVELS; ++l) {
        res.r[l] = (float)floor(16.0 * pow(b, (double)l));
    }

    int write_mask = (out_size >= (int)(NPTS * 32 + NPTS)) ? 1 : 0;
    float* mask_out = out + (size_t)NPTS * 32;

    k_zero<<<(NBINS + 255) / 256, 256>>>();
    k_count<<<(NPTS + 255) / 256, 256>>>(x, bbox, mask_out, write_mask);
    k_offsets<<<(NBINS + 255) / 256, 256>>>();
    k_scatter<<<(NPTS + 255) / 256, 256>>>(x);

    int total_threads = NPTS * 4;
    int blocks = (total_threads + 255) / 256;
    hash_embed_kernel<<<blocks, 256>>>(emb, bbox, out, res);
}

// round 7
// speedup vs baseline: 1.2802x; 1.0600x over previous
#include <cuda_runtime.h>
#include <math.h>
#include <stdint.h>

#define N_LEVELS 16
#define TABLE_SIZE (1u << 19)
#define HASH_MASK 0x7FFFFu
#define NPTS 1048576
#define PRIME_Y 2654435761u
#define PRIME_Z 805459861u

#define BINS_PER_AXIS 64
#define NBINS (BINS_PER_AXIS * BINS_PER_AXIS * BINS_PER_AXIS)

struct ResArr { float r[N_LEVELS]; };

// Scratch (static device globals: allowed; no allocation APIs)
__device__ unsigned d_count[NBINS];   // counts, then exclusive offsets (in place)
__device__ unsigned d_slot[NPTS];     // (bin << 14) | rank-within-bin
__device__ float4   d_xs[NPTS];       // reordered points: (x, y, z, bits(point_id))
__device__ unsigned d_cursor;

__device__ __forceinline__ unsigned spread3(unsigned v) {
    v = (v | (v << 16)) & 0x030000FFu;
    v = (v | (v << 8))  & 0x0300F00Fu;
    v = (v | (v << 4))  & 0x030C30C3u;
    v = (v | (v << 2))  & 0x09249249u;
    return v;
}

__device__ __forceinline__ unsigned bin_of(float px, float py, float pz,
                                           float b0x, float b0y, float b0z,
                                           float ivx, float ivy, float ivz) {
    float ux = (px - b0x) * ivx;
    float uy = (py - b0y) * ivy;
    float uz = (pz - b0z) * ivz;
    int bx = min(BINS_PER_AXIS - 1, max(0, (int)floorf(ux * BINS_PER_AXIS)));
    int by = min(BINS_PER_AXIS - 1, max(0, (int)floorf(uy * BINS_PER_AXIS)));
    int bz = min(BINS_PER_AXIS - 1, max(0, (int)floorf(uz * BINS_PER_AXIS)));
    return spread3((unsigned)bx) | (spread3((unsigned)by) << 1) | (spread3((unsigned)bz) << 2);
}

__global__ void k_zero() {
    int i = blockIdx.x * blockDim.x + threadIdx.x;
    if (i < NBINS) d_count[i] = 0u;
    if (i == 0) d_cursor = 0u;
}

__global__ void k_count(const float* __restrict__ x,
                        const float* __restrict__ bbox,
                        float* __restrict__ mask_out, int write_mask) {
    int i = blockIdx.x * blockDim.x + threadIdx.x;
    if (i >= NPTS) return;
    float b0x = __ldg(bbox + 0), b0y = __ldg(bbox + 1), b0z = __ldg(bbox + 2);
    float b1x = __ldg(bbox + 3), b1y = __ldg(bbox + 4), b1z = __ldg(bbox + 5);
    float px = __ldg(x + 3 * i + 0);
    float py = __ldg(x + 3 * i + 1);
    float pz = __ldg(x + 3 * i + 2);
    if (write_mask) {
        bool m = (px >= b0x) && (px <= b1x) && (py >= b0y) && (py <= b1y) &&
                 (pz >= b0z) && (pz <= b1z);
        mask_out[i] = m ? 1.0f : 0.0f;
    }
    float ivx = 1.0f / (b1x - b0x), ivy = 1.0f / (b1y - b0y), ivz = 1.0f / (b1z - b0z);
    unsigned b = bin_of(px, py, pz, b0x, b0y, b0z, ivx, ivy, ivz);
    unsigned rank = atomicAdd(&d_count[b], 1u);
    d_slot[i] = (b << 14) | (rank & 0x3FFFu);
}

__global__ void k_offsets() {
    int t = blockIdx.x * blockDim.x + threadIdx.x;
    if (t >= NBINS) return;
    int lane = threadIdx.x & 31;
    unsigned v = d_count[t];
    unsigned pre = v;
#pragma unroll
    for (int d = 1; d < 32; d <<= 1) {
        unsigned n = __shfl_up_sync(0xFFFFFFFFu, pre, d);
        if (lane >= d) pre += n;
    }
    unsigned total = __shfl_sync(0xFFFFFFFFu, pre, 31);
    unsigned base = 0;
    if (lane == 31) base = atomicAdd(&d_cursor, total);
    base = __shfl_sync(0xFFFFFFFFu, base, 31);
    d_count[t] = base + pre - v;   // exclusive offset
}

__global__ void k_scatter(const float* __restrict__ x) {
    int i = blockIdx.x * blockDim.x + threadIdx.x;
    if (i >= NPTS) return;
    unsigned s = d_slot[i];
    unsigned b = s >> 14;
    unsigned rank = s & 0x3FFFu;
    unsigned dst = d_count[b] + rank;
    float px = __ldg(x + 3 * i + 0);
    float py = __ldg(x + 3 * i + 1);
    float pz = __ldg(x + 3 * i + 2);
    d_xs[dst] = make_float4(px, py, pz, __uint_as_float((unsigned)i));
}

// Thread = (point, level-half, x-side). Warp = 16 points x 2 x-sides, so for
// every corner-load instruction, adjacent lanes hold the two x-corner table
// indices j and j^m of the SAME (y,z) corner -> they share a 128B line for
// even ix (m=1) and most odd ix (m=3,7) and the L1 coalescer merges them.
// Each lane yz-interps its 4 corners, scales by its x-weight, and one
// shfl_xor completes the trilinear lerp. Results staged via smem so global
// stores stay fully coalesced per point.
__global__ void __launch_bounds__(256) hash_embed_kernel(
    const float2* __restrict__ emb,
    const float* __restrict__ bbox,
    float* __restrict__ out,
    ResArr res)
{
    __shared__ float s_out[64][36];     // [point][32 feats + pad]
    __shared__ unsigned s_id[64];

    int t = threadIdx.x;
    int w = t >> 5, lane = t & 31;
    int pgroup = w >> 1, lhalf = w & 1;  // lhalf: levels [lhalf*8, lhalf*8+8)
    int q = lane >> 1, side = lane & 1;  // q: point within warp, side: x corner
    int lpt = pgroup * 16 + q;           // local point 0..63
    int point = blockIdx.x * 64 + lpt;

    float4 P = __ldg(&d_xs[point]);
    float px = P.x, py = P.y, pz = P.z;
    if (side == 0 && lhalf == 0) s_id[lpt] = __float_as_uint(P.w);

    float b0x = __ldg(bbox + 0), b0y = __ldg(bbox + 1), b0z = __ldg(bbox + 2);
    float b1x = __ldg(bbox + 3), b1y = __ldg(bbox + 4), b1z = __ldg(bbox + 5);

    float cx = fminf(fmaxf(px, b0x), b1x);
    float cy = fminf(fmaxf(py, b0y), b1y);
    float cz = fminf(fmaxf(pz, b0z), b1z);

    float invx = 1.0f / (b1x - b0x);
    float invy = 1.0f / (b1y - b0y);
    float invz = 1.0f / (b1z - b0z);

    float ux = (cx - b0x) * invx;
    float uy = (cy - b0y) * invy;
    float uz = (cz - b0z) * invz;
    float gx = (px - b0x) * invx;   // w numerator uses UNCLIPPED x (matches ref)
    float gy = (py - b0y) * invy;
    float gz = (pz - b0z) * invz;

    float accx[8], accy[8];

#pragma unroll
    for (int j = 0; j < 8; ++j) {
        int level = lhalf * 8 + j;
        float r = res.r[level];

        float fx = floorf(ux * r), fy = floorf(uy * r), fz = floorf(uz * r);
        float wx = fmaf(gx, r, -fx);
        float wy = fmaf(gy, r, -fy);
        float wz = fmaf(gz, r, -fz);

        unsigned ix = (unsigned)(int)fx + (unsigned)side;
        unsigned iy = (unsigned)(int)fy;
        unsigned iz = (unsigned)(int)fz;
        unsigned hy0 = iy * PRIME_Y, hy1 = hy0 + PRIME_Y;
        unsigned hz0 = iz * PRIME_Z, hz1 = hz0 + PRIME_Z;

        const float2* t2 = emb + (size_t)level * TABLE_SIZE;

        // this side's 4 corners, (y,z) = 00,01,10,11 — same instruction order
        // in both lanes of a pair so the pairwise line-merge happens
        float2 v0 = __ldg(t2 + ((ix ^ hy0 ^ hz0) & HASH_MASK));
        float2 v1 = __ldg(t2 + ((ix ^ hy0 ^ hz1) & HASH_MASK));
        float2 v2 = __ldg(t2 + ((ix ^ hy1 ^ hz0) & HASH_MASK));
        float2 v3 = __ldg(t2 + ((ix ^ hy1 ^ hz1) & HASH_MASK));

        float oy = 1.0f - wy, oz = 1.0f - wz;
        float xw = side ? wx : (1.0f - wx);

        // yz-interp of this side's corners, then x-weight; partner lane adds
        float c0a = v0.x * oy + v2.x * wy, c0b = v0.y * oy + v2.y * wy;
        float c1a = v1.x * oy + v3.x * wy, c1b = v1.y * oy + v3.y * wy;
        float sa = (c0a * oz + c1a * wz) * xw;
        float sb = (c0b * oz + c1b * wz) * xw;

        sa += __shfl_xor_sync(0xFFFFFFFFu, sa, 1);
        sb += __shfl_xor_sync(0xFFFFFFFFu, sb, 1);

        accx[j] = sa;
        accy[j] = sb;
    }

    // Stage to smem: side 0 writes its levels j=0..3, side 1 writes j=4..7.
    // Both lanes hold identical final values after the shfl-add.
    {
        int jbase = side * 4;
        float* dst = &s_out[lpt][lhalf * 16 + side * 8];   // 16B aligned
        float4* d4 = (float4*)dst;
        d4[0] = make_float4(accx[jbase + 0], accy[jbase + 0],
                            accx[jbase + 1], accy[jbase + 1]);
        d4[1] = make_float4(accx[jbase + 2], accy[jbase + 2],
                            accx[jbase + 3], accy[jbase + 3]);
    }

    __syncthreads();

    // Coalesced write-out: 64 points x 8 float4 chunks = 512 tasks, 2 per thread
#pragma unroll
    for (int k = 0; k < 2; ++k) {
        int idx = t + k * 256;
        int pt = idx >> 3, c = idx & 7;
        const float* s = &s_out[pt][c * 4];
        float4 val = make_float4(s[0], s[1], s[2], s[3]);
        unsigned opid = s_id[pt];
        *(float4*)(out + (size_t)opid * 32 + c * 4) = val;
    }
}

extern "C" void kernel_launch(void* const* d_in, const int* in_sizes, int n_in,
                              void* d_out, int out_size) {
    const float*  x    = (const float*)d_in[0];
    const float2* emb  = (const float2*)d_in[1];
    const float*  bbox = (const float*)d_in[2];
    float* out = (float*)d_out;

    // Resolutions: replicate numpy's double-precision exp/log/pow exactly.
    ResArr res;
    double b = exp((log(512.0) - log(16.0)) / 15.0);
    for (int l = 0; l < N_LEVELS; ++l) {
        res.r[l] = (float)floor(16.0 * pow(b, (double)l));
    }

    int write_mask = (out_size >= (int)(NPTS * 32 + NPTS)) ? 1 : 0;
    float* mask_out = out + (size_t)NPTS * 32;

    k_zero<<<(NBINS + 255) / 256, 256>>>();
    k_count<<<(NPTS + 255) / 256, 256>>>(x, bbox, mask_out, write_mask);
    k_offsets<<<(NBINS + 255) / 256, 256>>>();
    k_scatter<<<(NPTS + 255) / 256, 256>>>(x);

    // 64 points per block, 4 threads per point (2 level-halves x 2 x-sides)
    hash_embed_kernel<<<NPTS / 64, 256>>>(emb, bbox, out, res);
}